// round 15
// baseline (speedup 1.0000x reference)
#include <cuda_runtime.h>

// Sineconv: out[b,l,f] = sum_{w=0}^{64} x[b, l + 2f + ((f+w)>>5)] * sines[f, l+w]
//                        + x[b, l+32] * res_kernel[f]
// sines[f,s] = amplitude[f] * sin( ((frequency[f]*19000)*2pi) * sine_range[s] + phases[f]*2pi )
//
// x factor is piecewise-constant in w over 3 ranges -> each output needs
// 3 contiguous range-sums of sines (local fp32 prefix scan) + residual.
//
// R15: 255 CTAs x 1024 threads, FG=32 (all feature rows in one CTA; warp w
// owns row w with the R9-proven scan). Loaded SMs: 2 CTAs = 64 warps = 100%
// occupancy (launch_bounds(1024,2), regs budget 32). Epilogue lane = f ->
// perfect 128B-coalesced stores. Smallest grid -> smallest wall gap.

#define S_TOTAL 16384
#define L_OUT   16320
#define F_N     32
#define B_N     4
#define TILE_L  64
#define FG      32              // features per block (all)
#define NPP     132             // Psh row stride (16B-aligned rows)
#define XW      132             // xsh row stride (only 0..127 used)

// Accurate sinf via fp32 FMA Cody-Waite (exact internal products).
// |arg| <= ~1e5 here: total reduction error ~6e-8 rad.
__device__ __forceinline__ float acc_sinf(float a) {
    float kf = rintf(a * 0.63661977236758134f);          // 2/pi
    float r  = fmaf(-kf, 1.57079637050628662e+0f, a);    // c1 = float(pi/2)
    r        = fmaf(-kf, -4.37113900018624283e-8f, r);   // c2 = float(pi/2 - c1)
    int   q  = (int)kf;
    float r2 = r * r;
    float sp = fmaf(r2, fmaf(r2, fmaf(r2, -1.9841269841e-4f, 8.3333333333e-3f),
                             -1.6666666667e-1f), 1.0f);
    float s  = r * sp;
    float c  = fmaf(r2, fmaf(r2, fmaf(r2, fmaf(r2, 2.4801587302e-5f, -1.3888888889e-3f),
                             4.1666666667e-2f), -5.0e-1f), 1.0f);
    float v = (q & 1) ? c : s;
    return (q & 2) ? -v : v;
}

__global__ __launch_bounds__(1024, 2) void sineconv_kernel(
    const float* __restrict__ x,          // (B, S, 1)
    const float* __restrict__ sr,         // (S,)
    const float* __restrict__ phases,     // (32,)
    const float* __restrict__ amplitude,  // (32,)
    const float* __restrict__ frequency,  // (32,)
    const float* __restrict__ res_kernel, // (32,)
    float* __restrict__ out)              // (B, L, F)
{
    __shared__ __align__(16) float Psh[FG][NPP];  // Psh[w][j] = excl prefix before sample j
    __shared__ __align__(16) float xsh[B_N][XW];

    const int tid  = threadIdx.x;
    const int lane = tid & 31;
    const int warp = tid >> 5;       // 0..31 = feature row
    const int s0   = blockIdx.x * TILE_L;

    // ---- stage x: exactly 128 floats per batch (max index read = 127).
    // tid<128: one LDG.128 + one STS.128. Always in-bounds (s0+127 <= 16383).
    if (tid < 128) {
        int b = tid >> 5;
        int j = tid & 31;
        float4 v = ((const float4*)(x + b * S_TOTAL + s0))[j];
        *((float4*)&xsh[b][4 * j]) = v;
    }

    // ---- sines + fp32 prefix scan; warp w owns feature row w ----
    {
        const float TWO_PI = 6.28318530717958647692f;
        const int f = warp;
        // Replicate reference fp32 rounding: ((freq*19000)*2pi)*sr + ph
        float w2  = __fmul_rn(__fmul_rn(frequency[f], 19000.0f), TWO_PI);
        float ph  = __fmul_rn(phases[f], TWO_PI);
        float amp = amplitude[f];

        // lane's 4 consecutive samples via one LDG.128 (s0+127 <= 16383 always)
        float4 sv = ((const float4*)(sr + s0))[lane];
        float v0 = __fmul_rn(amp, acc_sinf(__fadd_rn(__fmul_rn(w2, sv.x), ph)));
        float v1 = __fmul_rn(amp, acc_sinf(__fadd_rn(__fmul_rn(w2, sv.y), ph)));
        float v2 = __fmul_rn(amp, acc_sinf(__fadd_rn(__fmul_rn(w2, sv.z), ph)));
        float v3 = __fmul_rn(amp, acc_sinf(__fadd_rn(__fmul_rn(w2, sv.w), ph)));
        float loc0 = v0;
        float loc1 = loc0 + v1;
        float loc2 = loc1 + v2;
        float run  = loc2 + v3;
        // exclusive scan of lane totals across the warp
        float t = run;
#pragma unroll
        for (int off = 1; off < 32; off <<= 1) {
            float n = __shfl_up_sync(0xFFFFFFFFu, t, off);
            if (lane >= off) t += n;
        }
        float excl = t - run;     // exclusive prefix before sample 4*lane
        // one aligned STS.128: exclusive prefixes at indices 4*lane .. 4*lane+3
        float4 w4;
        w4.x = excl;
        w4.y = excl + loc0;
        w4.z = excl + loc1;
        w4.w = excl + loc2;
        *((float4*)&Psh[warp][4 * lane]) = w4;
        if (lane == 31) Psh[warp][128] = excl + run;   // max index read is 128
    }
    __syncthreads();

    // ---- epilogue: thread -> (f = tid&31, i0 = tid>>5), 2 l-passes x 4 batches.
    // lane = f -> out stores are perfectly 128B-coalesced per warp.
    const int f  = tid & 31;
    const int i0 = tid >> 5;             // 0..31
    const float rk = res_kernel[f];
    const int i32 = 32 - f;
    const int i64 = 64 - f;

#pragma unroll
    for (int p = 0; p < 2; p++) {
        int i = i0 + p * 32;             // local l index, 0..63
        int l = s0 + i;                  // grid exact: l < L_OUT always
        float p0 = Psh[f][i];
        float pa = Psh[f][i + i32];
        float pb = Psh[f][i + i64];
        float p3 = Psh[f][i + 65];
        float A0 = pa - p0;              // sum sines[f, l .. l+31-f]
        float A1 = pb - pa;              // sum sines[f, l+32-f .. l+63-f]
        float A2 = p3 - pb;              // sum sines[f, l+64-f .. l+64]
        int xb = i + 2 * f;
#pragma unroll
        for (int b = 0; b < B_N; b++) {
            float r = fmaf(xsh[b][xb],     A0,
                      fmaf(xsh[b][xb + 1], A1,
                      fmaf(xsh[b][xb + 2], A2,
                           xsh[b][i + 32] * rk)));
            out[(b * L_OUT + l) * F_N + f] = r;
        }
    }
}

extern "C" void kernel_launch(void* const* d_in, const int* in_sizes, int n_in,
                              void* d_out, int out_size) {
    const float* x    = (const float*)d_in[0];
    const float* sr   = (const float*)d_in[1];
    const float* ph   = (const float*)d_in[2];
    const float* amp  = (const float*)d_in[3];
    const float* freq = (const float*)d_in[4];
    const float* rk   = (const float*)d_in[5];
    float* out = (float*)d_out;

    sineconv_kernel<<<L_OUT / TILE_L, 1024>>>(x, sr, ph, amp, freq, rk, out);
}

// round 16
// speedup vs baseline: 1.2741x; 1.2741x over previous
#include <cuda_runtime.h>
#include <cstdint>

// Sineconv: out[b,l,f] = sum_{w=0}^{64} x[b, l + 2f + ((f+w)>>5)] * sines[f, l+w]
//                        + x[b, l+32] * res_kernel[f]
// sines[f,s] = amplitude[f] * sin( ((frequency[f]*19000)*2pi) * sine_range[s] + phases[f]*2pi )
//
// x factor is piecewise-constant in w over 3 ranges -> each output needs
// 3 contiguous range-sums of sines (local fp32 prefix scan) + residual.
//
// R16: R9 skeleton (proven optimum: 256 thr, FG=8, 1020 CTAs, one wave at 7
// CTAs/SM) with the sine phase rebuilt on sm_103a packed f32x2 (FFMA2 via
// PTX): 2 sines per packed op, magic-constant round (kills FRND+F2I 20cyc
// chains), quadrant bits straight from the mantissa. Per-half f32x2 rounding
// == scalar __fmul_rn/fmaf, so reference fp32 arg rounding is bit-preserved.

#define S_TOTAL 16384
#define L_OUT   16320
#define F_N     32
#define B_N     4
#define TILE_L  64
#define FG      8               // features per block
#define NPP     132             // Psh row stride (16B-aligned rows)
#define XW      132             // xsh row stride (only 0..127 used)

typedef unsigned long long u64_t;

#define PACK2(d, lo, hi)   asm("mov.b64 %0, {%1, %2};" : "=l"(d) : "f"(lo), "f"(hi))
#define UNPK2F(lo, hi, s)  asm("mov.b64 {%0, %1}, %2;" : "=f"(lo), "=f"(hi) : "l"(s))
#define UNPK2U(lo, hi, s)  asm("mov.b64 {%0, %1}, %2;" : "=r"(lo), "=r"(hi) : "l"(s))
#define MUL2(d, a, b)      asm("mul.rn.f32x2 %0, %1, %2;" : "=l"(d) : "l"(a), "l"(b))
#define ADD2(d, a, b)      asm("add.rn.f32x2 %0, %1, %2;" : "=l"(d) : "l"(a), "l"(b))
#define FMA2(d, a, b, c)   asm("fma.rn.f32x2 %0, %1, %2, %3;" : "=l"(d) : "l"(a), "l"(b), "l"(c))

__device__ __forceinline__ u64_t cpair(float v) { u64_t d; PACK2(d, v, v); return d; }

// Two sines at once: o{0,1} = amp * sin(arg{lo,hi}), arg = fl(fl(w2*sr)+ph).
// Reduction: kb = fma(arg, 2/pi, 1.5*2^23) -> RNE integer; q = bits(kb)&3;
// k = kb - magic (exact); r = fma(k,-c1,arg); r = fma(k,c2,r). |k| <= 2^15.
__device__ __forceinline__ void sin2(u64_t sr2, u64_t W2, u64_t PH, u64_t AMP,
                                     float& o0, float& o1) {
    const u64_t C2OPI = cpair(0.63661977236758134f);
    const u64_t MAGIC = cpair(12582912.0f);            // 1.5 * 2^23
    const u64_t NMAGIC= cpair(-12582912.0f);
    const u64_t NC1   = cpair(-1.57079637050628662e+0f);  // -float(pi/2)
    const u64_t C2    = cpair(4.37113900018624283e-8f);   // -(pi/2 - c1)
    const u64_t S3 = cpair(-1.9841269841e-4f), S2 = cpair(8.3333333333e-3f);
    const u64_t S1 = cpair(-1.6666666667e-1f), ONE = cpair(1.0f);
    const u64_t K4 = cpair(2.4801587302e-5f),  K3 = cpair(-1.3888888889e-3f);
    const u64_t K2 = cpair(4.1666666667e-2f),  NH = cpair(-5.0e-1f);

    u64_t t, arg, kb, kf, r, r2, sp, cp, sa, ca;
    MUL2(t, W2, sr2);          // per-half == __fmul_rn(w2, sr)
    ADD2(arg, t, PH);          // per-half == __fadd_rn(., ph)
    FMA2(kb, arg, C2OPI, MAGIC);
    unsigned qlo, qhi;
    UNPK2U(qlo, qhi, kb);      // bits ≡ k (mod 4), two's complement safe
    ADD2(kf, kb, NMAGIC);      // exact: k as packed floats
    FMA2(r, kf, NC1, arg);
    FMA2(r, kf, C2, r);
    MUL2(r2, r, r);
    FMA2(sp, r2, S3, S2);      // sin poly
    FMA2(sp, r2, sp, S1);
    FMA2(sp, r2, sp, ONE);
    MUL2(sp, r, sp);
    FMA2(cp, r2, K4, K3);      // cos poly
    FMA2(cp, r2, cp, K2);
    FMA2(cp, r2, cp, NH);
    FMA2(cp, r2, cp, ONE);
    MUL2(sa, sp, AMP);         // amp*(sin|cos); select commutes with mul/sign
    MUL2(ca, cp, AMP);
    float slo, shi, clo, chi;
    UNPK2F(slo, shi, sa);
    UNPK2F(clo, chi, ca);
    float v0 = (qlo & 1u) ? clo : slo;
    float v1 = (qhi & 1u) ? chi : shi;
    o0 = __uint_as_float(__float_as_uint(v0) ^ ((qlo & 2u) << 30));
    o1 = __uint_as_float(__float_as_uint(v1) ^ ((qhi & 2u) << 30));
}

__global__ __launch_bounds__(256, 7) void sineconv_kernel(
    const float* __restrict__ x,          // (B, S, 1)
    const float* __restrict__ sr,         // (S,)
    const float* __restrict__ phases,     // (32,)
    const float* __restrict__ amplitude,  // (32,)
    const float* __restrict__ frequency,  // (32,)
    const float* __restrict__ res_kernel, // (32,)
    float* __restrict__ out)              // (B, L, F)
{
    __shared__ __align__(16) float Psh[FG][NPP];  // Psh[w][j] = excl prefix before sample j
    __shared__ __align__(16) float xsh[B_N][XW];

    const int tid  = threadIdx.x;
    const int lane = tid & 31;
    const int warp = tid >> 5;
    const int s0   = blockIdx.x * TILE_L;
    const int fg0  = blockIdx.y * FG;

    // ---- stage x: exactly 128 floats per batch (max index read = 127).
    // tid<128: one LDG.128 + one STS.128. Always in-bounds (s0+127 <= 16383).
    if (tid < 128) {
        int b = tid >> 5;
        int j = tid & 31;
        float4 v = ((const float4*)(x + b * S_TOTAL + s0))[j];
        *((float4*)&xsh[b][4 * j]) = v;
    }

    // ---- sines (packed f32x2) + fp32 prefix scan; warp w owns row fg0+w ----
    {
        const float TWO_PI = 6.28318530717958647692f;
        const int f = fg0 + warp;
        // Replicate reference fp32 rounding: ((freq*19000)*2pi)*sr + ph
        float w2  = __fmul_rn(__fmul_rn(frequency[f], 19000.0f), TWO_PI);
        float ph  = __fmul_rn(phases[f], TWO_PI);
        float amp = amplitude[f];
        u64_t W2p, PHp, AMPp;
        PACK2(W2p, w2, w2);
        PACK2(PHp, ph, ph);
        PACK2(AMPp, amp, amp);

        // lane's 4 consecutive samples via one LDG.128 (s0+127 <= 16383 always)
        float4 sv = ((const float4*)(sr + s0))[lane];
        u64_t sr01, sr23;
        PACK2(sr01, sv.x, sv.y);
        PACK2(sr23, sv.z, sv.w);
        float v0, v1, v2, v3;
        sin2(sr01, W2p, PHp, AMPp, v0, v1);
        sin2(sr23, W2p, PHp, AMPp, v2, v3);

        float loc0 = v0;
        float loc1 = loc0 + v1;
        float loc2 = loc1 + v2;
        float run  = loc2 + v3;
        // exclusive scan of lane totals across the warp
        float t = run;
#pragma unroll
        for (int off = 1; off < 32; off <<= 1) {
            float n = __shfl_up_sync(0xFFFFFFFFu, t, off);
            if (lane >= off) t += n;
        }
        float excl = t - run;     // exclusive prefix before sample 4*lane
        // one aligned STS.128: exclusive prefixes at indices 4*lane .. 4*lane+3
        float4 w4;
        w4.x = excl;
        w4.y = excl + loc0;
        w4.z = excl + loc1;
        w4.w = excl + loc2;
        *((float4*)&Psh[warp][4 * lane]) = w4;
        if (lane == 31) Psh[warp][128] = excl + run;   // max index read is 128
    }
    __syncthreads();

    // ---- epilogue: thread -> (fl = tid&7, i0 = tid>>3), 2 l-passes x 4 batches ----
    const int fl = tid & 7;
    const int f  = fg0 + fl;
    const int i0 = tid >> 3;             // 0..31
    const float rk = res_kernel[f];
    const int i32 = 32 - f;
    const int i64 = 64 - f;

#pragma unroll
    for (int p = 0; p < 2; p++) {
        int i = i0 + p * 32;             // local l index, 0..63
        int l = s0 + i;                  // grid exact: l < L_OUT always
        float p0 = Psh[fl][i];
        float pa = Psh[fl][i + i32];
        float pb = Psh[fl][i + i64];
        float p3 = Psh[fl][i + 65];
        float A0 = pa - p0;              // sum sines[f, l .. l+31-f]
        float A1 = pb - pa;              // sum sines[f, l+32-f .. l+63-f]
        float A2 = p3 - pb;              // sum sines[f, l+64-f .. l+64]
        int xb = i + 2 * f;
#pragma unroll
        for (int b = 0; b < B_N; b++) {
            float r = fmaf(xsh[b][xb],     A0,
                      fmaf(xsh[b][xb + 1], A1,
                      fmaf(xsh[b][xb + 2], A2,
                           xsh[b][i + 32] * rk)));
            out[(b * L_OUT + l) * F_N + f] = r;
        }
    }
}

extern "C" void kernel_launch(void* const* d_in, const int* in_sizes, int n_in,
                              void* d_out, int out_size) {
    const float* x    = (const float*)d_in[0];
    const float* sr   = (const float*)d_in[1];
    const float* ph   = (const float*)d_in[2];
    const float* amp  = (const float*)d_in[3];
    const float* freq = (const float*)d_in[4];
    const float* rk   = (const float*)d_in[5];
    float* out = (float*)d_out;

    dim3 grid(L_OUT / TILE_L, F_N / FG);   // (255, 4) = 1020 CTAs
    sineconv_kernel<<<grid, 256>>>(x, sr, ph, amp, freq, rk, out);
}